// round 17
// baseline (speedup 1.0000x reference)
#include <cuda_runtime.h>
#include <cstddef>

#define IMG_H 512
#define IMG_W 512
#define IMGF  (IMG_H * IMG_W * 3)
#define TILE_W 64
#define TILE_H 32
#define NP_TOT 1024
#define OUTF_PER_B (NP_TOT * 768)

__constant__ float c_w[81];   // [ky][kx][ci][co] HWIO

// Output-linear permuted pos_emb with bias folded in (batch-independent), 3 MB.
__device__ float d_pe_perm[OUTF_PER_B];

// ---- prep: vectorized permute (1 float4/thread), bias folded ----
__global__ __launch_bounds__(256)
void pe_permute_kernel(const float* __restrict__ pos_emb,
                       const float* __restrict__ bias)
{
    const int j4 = blockIdx.x * 256 + threadIdx.x;     // < 196608
    const int np  = j4 / 192;
    const int rm4 = j4 - np * 192;
    const int r   = rm4 / 12;
    const int k4  = rm4 - r * 12;
    const int gh  = ((np >> 5) << 4) + r;
    const int fc  = k4 / 3;
    const int sub = k4 - fc * 3;
    const int nf  = (gh >> 2) * 128 + ((np & 31) << 2) + fc;
    const int src4 = nf * 12 + (gh & 3) * 3 + sub;

    float4 v = ((const float4*)pos_emb)[src4];
    const float bb[3] = { bias[0], bias[1], bias[2] };
    const int c0 = k4 % 3;
    v.x += bb[c0];
    v.y += bb[(c0 + 1) % 3];
    v.z += bb[(c0 + 2) % 3];
    v.w += bb[c0];
    ((float4*)d_pe_perm)[j4] = v;
}

// Raw row load: 3 dense LDG.128 + predicated edge LDG. No dependencies on results.
__device__ __forceinline__ void load_raw(const float4* __restrict__ X4,
                                         int rq, bool rvalid, int txq,
                                         bool wleft, bool wright,
                                         float4& A, float4& B, float4& C, float4& E)
{
    A = make_float4(0.f,0.f,0.f,0.f);
    B = A; C = A; E = A;
    if (rvalid) {
        const int q0 = rq + 3 * txq;
        A = X4[q0];
        B = X4[q0 + 1];
        C = X4[q0 + 2];
        const bool left  = (txq == 0);
        const bool right = (txq == 15);
        if ((left && wleft) || (right && wright))
            E = X4[left ? (q0 - 1) : (q0 + 3)];
    }
}

// Shuffle halos + unpack into an 18-float window (consumes the loads).
__device__ __forceinline__ void make_win(const float4 A, const float4 B,
                                         const float4 C, const float4 E,
                                         int txq, float win[18])
{
    float L0 = __shfl_up_sync(0xffffffffu, C.y, 1, 16);
    float L1 = __shfl_up_sync(0xffffffffu, C.z, 1, 16);
    float L2 = __shfl_up_sync(0xffffffffu, C.w, 1, 16);
    float R0 = __shfl_down_sync(0xffffffffu, A.x, 1, 16);
    float R1 = __shfl_down_sync(0xffffffffu, A.y, 1, 16);
    float R2 = __shfl_down_sync(0xffffffffu, A.z, 1, 16);
    if (txq == 0)  { L0 = E.y; L1 = E.z; L2 = E.w; }
    if (txq == 15) { R0 = E.x; R1 = E.y; R2 = E.z; }

    win[0]  = L0;  win[1]  = L1;  win[2]  = L2;
    win[3]  = A.x; win[4]  = A.y; win[5]  = A.z; win[6]  = A.w;
    win[7]  = B.x; win[8]  = B.y; win[9]  = B.z; win[10] = B.w;
    win[11] = C.x; win[12] = C.y; win[13] = C.z; win[14] = C.w;
    win[15] = R0;  win[16] = R1;  win[17] = R2;
}

__device__ __forceinline__ void apply_row(const float win[18], float acc[12], const int wrow)
{
#pragma unroll
    for (int x = 0; x < 4; x++) {
#pragma unroll
        for (int dx = 0; dx < 3; dx++) {
#pragma unroll
            for (int ci = 0; ci < 3; ci++) {
                const float v = win[3*(x + dx) + ci];
                const int wb = ((wrow*3 + dx)*3 + ci)*3;
                acc[x*3 + 0] += v * c_w[wb + 0];
                acc[x*3 + 1] += v * c_w[wb + 1];
                acc[x*3 + 2] += v * c_w[wb + 2];
            }
        }
    }
}

__global__ __launch_bounds__(256, 3)
void patchenc_v9_kernel(const float* __restrict__ X,
                        float* __restrict__ out)
{
    __shared__ float4 sout4[1536];   // 24 KB, output-ordered

    const int b  = blockIdx.z;
    const int h0 = blockIdx.y * TILE_H;
    const int w0 = blockIdx.x * TILE_W;
    const float4* __restrict__ X4 = (const float4*)(X + (size_t)b * IMGF);

    const int txq = threadIdx.x & 15;
    const int tyq = threadIdx.x >> 4;
    const int gh0 = h0 + 2 * tyq;

    const bool wleft  = (w0 > 0);
    const bool wright = (w0 + TILE_W < IMG_W);
    const int wq = (3 * w0) >> 2;

    float acc0[12], acc1[12];
#pragma unroll
    for (int i = 0; i < 12; i++) { acc0[i] = 0.f; acc1[i] = 0.f; }

    // ---- depth-2 pipelined rows: gh0-1 .. gh0+2 ----
    float4 A0,B0,C0,E0, A1,B1,C1,E1;
    float win[18];

    load_raw(X4, 384*(gh0-1) + wq, gh0 >= 1,     txq, wleft, wright, A0,B0,C0,E0);
    load_raw(X4, 384*gh0     + wq, true,         txq, wleft, wright, A1,B1,C1,E1);

    make_win(A0,B0,C0,E0, txq, win);
    load_raw(X4, 384*(gh0+1) + wq, true,         txq, wleft, wright, A0,B0,C0,E0);
    apply_row(win, acc0, 0);

    make_win(A1,B1,C1,E1, txq, win);
    load_raw(X4, 384*(gh0+2) + wq, gh0+2 < IMG_H, txq, wleft, wright, A1,B1,C1,E1);
    apply_row(win, acc0, 1);
    apply_row(win, acc1, 0);

    make_win(A0,B0,C0,E0, txq, win);
    apply_row(win, acc0, 2);
    apply_row(win, acc1, 1);

    make_win(A1,B1,C1,E1, txq, win);
    apply_row(win, acc1, 2);

    // ---- stage into output-ordered smem ----
    const int band = tyq >> 3;
    const int pch  = txq >> 2;
#pragma unroll
    for (int k = 0; k < 2; k++) {
        const float* acc = (k == 0) ? acc0 : acc1;
        const int gh = gh0 + k;
        float4* so = &sout4[band * 768 + pch * 192 + (gh & 15) * 12 + (txq & 3) * 3];
        so[0] = make_float4(acc[0], acc[1],  acc[2],  acc[3]);
        so[1] = make_float4(acc[4], acc[5],  acc[6],  acc[7]);
        so[2] = make_float4(acc[8], acc[9],  acc[10], acc[11]);
    }

    __syncthreads();

    // ---- linear copy-out fused with linear PE(+bias) add ----
    const int npb0 = (h0 >> 4) * 32 + (w0 >> 4);
    const float4* pe4 = (const float4*)d_pe_perm;
    float4* ob = (float4*)out + (size_t)b * (OUTF_PER_B / 4);

#pragma unroll
    for (int k = 0; k < 6; k++) {
        const int v  = threadIdx.x + k * 256;        // 0..1535
        const int bd = (v >= 768) ? 1 : 0;
        const int rm = v - bd * 768;
        const size_t g4 = (size_t)(npb0 + bd * 32) * 192 + rm;
        float4 sv = sout4[v];
        float4 p  = pe4[g4];
        ob[g4] = make_float4(sv.x + p.x, sv.y + p.y, sv.z + p.z, sv.w + p.w);
    }
}

extern "C" void kernel_launch(void* const* d_in, const int* in_sizes, int n_in,
                              void* d_out, int out_size)
{
    const float* X  = (const float*)d_in[0];
    const float* Kw = (const float*)d_in[1];
    const float* Bb = (const float*)d_in[2];
    const float* PE = (const float*)d_in[3];

    cudaMemcpyToSymbolAsync(c_w, Kw, 81 * sizeof(float), 0, cudaMemcpyDeviceToDevice, 0);

    pe_permute_kernel<<<768, 256>>>(PE, Bb);

    dim3 grid(IMG_W / TILE_W, IMG_H / TILE_H, 32);
    patchenc_v9_kernel<<<grid, 256>>>(X, (float*)d_out);
}